// round 1
// baseline (speedup 1.0000x reference)
#include <cuda_runtime.h>
#include <cstdint>

#define BATCH 65536
#define INP 64
#define HID 128
#define NACT 16
#define BM 128
#define NTHR 256

// smem strides in floats; all ≡ 4 (mod 32) -> conflict-free mma fragment loads
#define XS 68
#define HS 132
#define WS 68

#define SMEM_FLOATS (BM * XS + 2 * BM * HS + 128 * WS + 128)
#define SMEM_BYTES (SMEM_FLOATS * 4)

__device__ __forceinline__ unsigned f2tf32(float v) {
    unsigned u;
    asm("cvt.rna.tf32.f32 %0, %1;" : "=r"(u) : "f"(v));
    return u;
}
__device__ __forceinline__ float fsig(float v) {
    float e = __expf(-v);
    return __fdividef(1.f, 1.f + e);
}
__device__ __forceinline__ float ftanh(float v) {
    float e = __expf(2.f * v);
    return __fdividef(e - 1.f, e + 1.f);
}

#define MMA_TF32(d, a0, a1, a2, a3, b0, b1)                                     \
    asm volatile(                                                               \
        "mma.sync.aligned.m16n8k8.row.col.f32.tf32.tf32.f32 "                   \
        "{%0,%1,%2,%3},{%4,%5,%6,%7},{%8,%9},{%0,%1,%2,%3};"                    \
        : "+f"(d[0]), "+f"(d[1]), "+f"(d[2]), "+f"(d[3])                        \
        : "r"(a0), "r"(a1), "r"(a2), "r"(a3), "r"(b0), "r"(b1))

__global__ void __launch_bounds__(NTHR, 1)
lstm_policy_kernel(const float* __restrict__ x,
                   const float* __restrict__ Wih0,
                   const float* __restrict__ bih0,
                   const float* __restrict__ bhh0,
                   const float* __restrict__ Wih1,
                   const float* __restrict__ bih1,
                   const float* __restrict__ bhh1,
                   const float* __restrict__ Wp,
                   const float* __restrict__ bp,
                   const float* __restrict__ Wv,
                   const float* __restrict__ bv,
                   float* __restrict__ out) {
    extern __shared__ float sm[];
    float* sX = sm;                 // [BM][XS]  x tile (tf32 bits)
    float* sT = sX + BM * XS;       // [BM][HS]  i-act, then c
    float* sH = sT + BM * HS;       // [BM][HS]  h0 (tf32 bits), then h1 (fp32)
    float* sW = sH + BM * HS;       // [128][WS] weight chunk (tf32 bits)
    float* sB = sW + 128 * WS;      // [128]     combined bias for panel

    const int tid = threadIdx.x;
    const int wid = tid >> 5, lane = tid & 31;
    const int g = lane >> 2, tg = lane & 3;
    const int mw = wid & 3, nw = wid >> 2;
    const int mrow = mw * 32, ncol = nw * 64;
    const int rowbase = blockIdx.x * BM;

    // ---- load x tile (rounded to tf32) ----
    {
        const float4* src = (const float4*)(x + (size_t)rowbase * INP);
#pragma unroll
        for (int i = 0; i < 8; i++) {
            int idx = tid + i * NTHR;  // 2048 float4 total
            int r = idx >> 4;          // 16 float4 per 64-col row
            int c4 = idx & 15;
            float4 v = src[idx];
            unsigned* dst = (unsigned*)(sX + r * XS + c4 * 4);
            dst[0] = f2tf32(v.x);
            dst[1] = f2tf32(v.y);
            dst[2] = f2tf32(v.z);
            dst[3] = f2tf32(v.w);
        }
    }

    // lambda: load one [128 x 64] weight chunk into sW (tf32-rounded)
    auto loadW = [&](const float* Wsrc, int gbase, int koff, int Ksrc) {
#pragma unroll
        for (int i = 0; i < 8; i++) {
            int idx = tid + i * NTHR;  // 2048 float4
            int r = idx >> 4;
            int c4 = idx & 15;
            const float4* srcp =
                (const float4*)(Wsrc + (size_t)(gbase + r) * Ksrc + koff + c4 * 4);
            float4 v = *srcp;
            unsigned* dst = (unsigned*)(sW + r * WS + c4 * 4);
            dst[0] = f2tf32(v.x);
            dst[1] = f2tf32(v.y);
            dst[2] = f2tf32(v.z);
            dst[3] = f2tf32(v.w);
        }
    };

    // lambda: one 8-kstep GEMM chunk, A from smem (stride AS, col offset koffA)
    auto gemmChunk = [&](const unsigned* uA, int AS, int koffA, float acc[2][8][4]) {
        const unsigned* uW = (const unsigned*)sW;
#pragma unroll
        for (int ks = 0; ks < 8; ks++) {
            unsigned af[2][4];
#pragma unroll
            for (int mt = 0; mt < 2; mt++) {
                const unsigned* base = uA + (mrow + mt * 16 + g) * AS + koffA + ks * 8 + tg;
                af[mt][0] = base[0];
                af[mt][1] = base[8 * AS];
                af[mt][2] = base[4];
                af[mt][3] = base[8 * AS + 4];
            }
#pragma unroll
            for (int nt = 0; nt < 8; nt++) {
                const unsigned* wb = uW + (ncol + nt * 8 + g) * WS + ks * 8 + tg;
                unsigned b0 = wb[0], b1 = wb[4];
#pragma unroll
                for (int mt = 0; mt < 2; mt++) {
                    MMA_TF32(acc[mt][nt], af[mt][0], af[mt][1], af[mt][2], af[mt][3], b0, b1);
                }
            }
        }
    };

    // lambda: run one layer (3 gate panels: i, g, o; f gate is dead since c=0)
    auto runLayer = [&](const unsigned* uA, int AS, int K, const float* Wsrc,
                        const float* bi, const float* bh, int layer) {
        const int nchunks = K / 64;
#pragma unroll 1
        for (int gate = 0; gate < 3; gate++) {
            const int gbase = (gate == 0) ? 0 : (gate == 1 ? 2 * HID : 3 * HID);
            float acc[2][8][4];
#pragma unroll
            for (int mt = 0; mt < 2; mt++)
#pragma unroll
                for (int nt = 0; nt < 8; nt++)
#pragma unroll
                    for (int ci = 0; ci < 4; ci++) acc[mt][nt][ci] = 0.f;

#pragma unroll 1
            for (int kc = 0; kc < nchunks; kc++) {
                __syncthreads();  // prior sW readers done / prior writes visible
                loadW(Wsrc, gbase, kc * 64, K);
                if (kc == 0 && tid < 128) sB[tid] = bi[gbase + tid] + bh[gbase + tid];
                __syncthreads();  // sW + sB ready
                gemmChunk(uA, AS, kc * 64, acc);
            }

            if (layer == 1 && gate == 2) __syncthreads();  // all h0 reads done before overwrite

            // epilogue: bias + activation, write to sT / sH
#pragma unroll
            for (int mt = 0; mt < 2; mt++)
#pragma unroll
                for (int nt = 0; nt < 8; nt++)
#pragma unroll
                    for (int ci = 0; ci < 4; ci++) {
                        int r = mrow + mt * 16 + g + ((ci >> 1) << 3);
                        int cc = ncol + nt * 8 + (tg << 1) + (ci & 1);
                        float v = acc[mt][nt][ci] + sB[cc];
                        int idx = r * HS + cc;
                        if (gate == 0) {
                            sT[idx] = fsig(v);
                        } else if (gate == 1) {
                            sT[idx] = sT[idx] * ftanh(v);  // c = sig(i)*tanh(g)
                        } else {
                            float h = fsig(v) * ftanh(sT[idx]);  // h = sig(o)*tanh(c)
                            // layer0: round h0 to tf32 (mma operand); layer1: keep fp32 for heads
                            sH[idx] = (layer == 0) ? __uint_as_float(f2tf32(h)) : h;
                        }
                    }
        }
    };

    // ---- layer 0: A = x (K=64), layer 1: A = h0 (K=128) ----
    runLayer((const unsigned*)sX, XS, INP, Wih0, bih0, bhh0, 0);
    runLayer((const unsigned*)sH, HS, HID, Wih1, bih1, bhh1, 1);

    __syncthreads();  // h1 ready in sH (fp32)

    // ---- heads: 17 outputs (16 policy + 1 value) per row, fp32 ----
    float* pol = out;
    float* val = out + (size_t)BATCH * NACT;
#pragma unroll 1
    for (int idx = tid; idx < BM * 17; idx += NTHR) {
        int r = idx / 17;
        int a = idx - r * 17;
        const float4* wrow = (const float4*)((a < NACT) ? (Wp + a * HID) : Wv);
        float bias = (a < NACT) ? bp[a] : bv[0];
        const float4* hrow = (const float4*)(sH + r * HS);
        float s = 0.f;
#pragma unroll
        for (int k4 = 0; k4 < HID / 4; k4++) {
            float4 hv = hrow[k4];
            float4 wv = wrow[k4];
            s += hv.x * wv.x + hv.y * wv.y + hv.z * wv.z + hv.w * wv.w;
        }
        s += bias;
        int gr = rowbase + r;
        if (a < NACT)
            pol[(size_t)gr * NACT + a] = s;
        else
            val[gr] = s;
    }
}

extern "C" void kernel_launch(void* const* d_in, const int* in_sizes, int n_in,
                              void* d_out, int out_size) {
    const float* x    = (const float*)d_in[0];
    const float* Wih0 = (const float*)d_in[1];
    // d_in[2] = Whh0: unused (h=0)
    const float* bih0 = (const float*)d_in[3];
    const float* bhh0 = (const float*)d_in[4];
    const float* Wih1 = (const float*)d_in[5];
    // d_in[6] = Whh1: unused (h=0)
    const float* bih1 = (const float*)d_in[7];
    const float* bhh1 = (const float*)d_in[8];
    const float* Wp   = (const float*)d_in[9];
    const float* bp   = (const float*)d_in[10];
    const float* Wv   = (const float*)d_in[11];
    const float* bv   = (const float*)d_in[12];
    float* out = (float*)d_out;

    cudaFuncSetAttribute(lstm_policy_kernel,
                         cudaFuncAttributeMaxDynamicSharedMemorySize, SMEM_BYTES);

    dim3 grid(BATCH / BM);
    dim3 block(NTHR);
    lstm_policy_kernel<<<grid, block, SMEM_BYTES>>>(
        x, Wih0, bih0, bhh0, Wih1, bih1, bhh1, Wp, bp, Wv, bv, out);
}

// round 3
// speedup vs baseline: 3.0492x; 3.0492x over previous
#include <cuda_runtime.h>
#include <cstdint>

#define BATCH 65536
#define INP 64
#define HID 128
#define NACT 16
#define BM 128
#define NTHR 512

// smem strides (floats); XS,WS ≡ 4 (mod 32), HS/WHS ≡ 4 (mod 32): conflict-free frags
#define XS 68
#define HS 132
#define WS 68
#define WHS 132

#define SX_OFF 0
#define SH_OFF (BM * XS)                      // 8704
#define SW_OFF (SH_OFF + BM * HS)             // 25600
#define CHUNK_FLOATS (128 * WS)               // 8704
#define SWH_OFF (SW_OFF + 2 * CHUNK_FLOATS)   // 43008
#define SB_OFF (SWH_OFF + 24 * WHS)           // 46176
#define SMEM_FLOATS (SB_OFF + 6 * 128)        // 46944
#define SMEM_BYTES (SMEM_FLOATS * 4)          // ~183 KB

__device__ __forceinline__ void cpa16(float* dst, const float* src) {
    unsigned u = (unsigned)__cvta_generic_to_shared(dst);
    asm volatile("cp.async.cg.shared.global [%0], [%1], 16;" ::"r"(u), "l"(src));
}
__device__ __forceinline__ void cpcommit() { asm volatile("cp.async.commit_group;"); }

__device__ __forceinline__ float fsig(float v) {
    float e = __expf(-v);
    return __fdividef(1.f, 1.f + e);
}
__device__ __forceinline__ float ftanh(float v) {
    float e = __expf(2.f * v);
    return __fdividef(e - 1.f, e + 1.f);
}

#define MMA_TF32(d, a0, a1, a2, a3, b0, b1)                                     \
    asm volatile(                                                               \
        "mma.sync.aligned.m16n8k8.row.col.f32.tf32.tf32.f32 "                   \
        "{%0,%1,%2,%3},{%4,%5,%6,%7},{%8,%9},{%0,%1,%2,%3};"                    \
        : "+f"(d[0]), "+f"(d[1]), "+f"(d[2]), "+f"(d[3])                        \
        : "r"(a0), "r"(a1), "r"(a2), "r"(a3), "r"(b0), "r"(b1))

#define WAITSYNC(N)                                           \
    do {                                                      \
        asm volatile("cp.async.wait_group %0;" ::"n"(N));     \
        __syncthreads();                                      \
    } while (0)

__global__ void __launch_bounds__(NTHR, 1)
lstm_policy_kernel(const float* __restrict__ x,
                   const float* __restrict__ Wih0,
                   const float* __restrict__ bih0,
                   const float* __restrict__ bhh0,
                   const float* __restrict__ Wih1,
                   const float* __restrict__ bih1,
                   const float* __restrict__ bhh1,
                   const float* __restrict__ Wp,
                   const float* __restrict__ bp,
                   const float* __restrict__ Wv,
                   const float* __restrict__ bv,
                   float* __restrict__ out) {
    extern __shared__ float sm[];
    float* sX = sm + SX_OFF;
    float* sH = sm + SH_OFF;
    float* sW0 = sm + SW_OFF;
    float* sW1 = sm + SW_OFF + CHUNK_FLOATS;
    float* sWH = sm + SWH_OFF;
    float* sB = sm + SB_OFF;

    const int tid = threadIdx.x;
    const int wid = tid >> 5, lane = tid & 31;
    const int g = lane >> 2, tg = lane & 3;
    const int mrow = (wid & 3) * 32;   // 4 row-groups of 32
    const int ncolW = (wid >> 2) * 32; // 4 col-groups of 32
    const int rowbase = blockIdx.x * BM;

    // prefetch one [128 x 64] weight chunk into a buffer
    auto prefW = [&](const float* src, int ld, float* dst) {
#pragma unroll
        for (int i = 0; i < 4; i++) {
            int idx = tid + i * NTHR;  // 2048 float4
            int r = idx >> 4;
            int c4 = idx & 15;
            cpa16(dst + r * WS + c4 * 4, src + (size_t)r * ld + c4 * 4);
        }
    };

    // ---- start async pipeline: group0 = x + head weights + chunk0, group1 = chunk1
    {
        const float* xs = x + (size_t)rowbase * INP;
#pragma unroll
        for (int i = 0; i < 4; i++) {
            int idx = tid + i * NTHR;
            int r = idx >> 4;
            int c4 = idx & 15;
            cpa16(sX + r * XS + c4 * 4, xs + r * INP + c4 * 4);
        }
        // 17 rows x 32 float4 = 544 loads > NTHR: MUST loop (this was the R2 bug:
        // `if (tid < 544)` with 512 threads never loaded row 16 = Wv)
#pragma unroll
        for (int idx = tid; idx < 544; idx += NTHR) {
            int r = idx >> 5, c4 = idx & 31;
            const float* srcp = (r < 16) ? (Wp + r * HID + c4 * 4) : (Wv + c4 * 4);
            cpa16(sWH + r * WHS + c4 * 4, srcp);
        }
        prefW(Wih0, INP, sW0);  // chunk0: L0 gate-i
        cpcommit();
        prefW(Wih0 + 256 * INP, INP, sW1);  // chunk1: L0 gate-g
        cpcommit();
    }

    // biases (combined) + zero-pad head weight rows 17..23
    if (tid < 128) {
        sB[tid] = bih0[tid] + bhh0[tid];
        sB[128 + tid] = bih0[256 + tid] + bhh0[256 + tid];
        sB[256 + tid] = bih0[384 + tid] + bhh0[384 + tid];
        sB[384 + tid] = bih1[tid] + bhh1[tid];
        sB[512 + tid] = bih1[256 + tid] + bhh1[256 + tid];
        sB[640 + tid] = bih1[384 + tid] + bhh1[384 + tid];
    }
#pragma unroll
    for (int idx = tid; idx < 7 * HID; idx += NTHR) {
        int r = 17 + idx / HID, c = idx % HID;
        sWH[r * WHS + c] = 0.f;
    }

    float acc[2][4][4], sc[2][4][4];
#pragma unroll
    for (int mt = 0; mt < 2; mt++)
#pragma unroll
        for (int nt = 0; nt < 4; nt++)
#pragma unroll
            for (int ci = 0; ci < 4; ci++) acc[mt][nt][ci] = 0.f;

    // one 64-K gemm chunk into acc; warp tile 32x32 (2 mt x 4 nt)
    auto gemmChunk = [&](const float* A, int AS_, int koffA, const float* Wbuf) {
        const unsigned* uA = (const unsigned*)A;
        const unsigned* uW = (const unsigned*)Wbuf;
#pragma unroll
        for (int ks = 0; ks < 8; ks++) {
            unsigned af[2][4];
#pragma unroll
            for (int mt = 0; mt < 2; mt++) {
                const unsigned* base = uA + (mrow + mt * 16 + g) * AS_ + koffA + ks * 8 + tg;
                af[mt][0] = base[0];
                af[mt][1] = base[8 * AS_];
                af[mt][2] = base[4];
                af[mt][3] = base[8 * AS_ + 4];
            }
#pragma unroll
            for (int nt = 0; nt < 4; nt++) {
                const unsigned* wb = uW + (ncolW + nt * 8 + g) * WS + ks * 8 + tg;
                unsigned b0 = wb[0], b1 = wb[4];
#pragma unroll
                for (int mt = 0; mt < 2; mt++)
                    MMA_TF32(acc[mt][nt], af[mt][0], af[mt][1], af[mt][2], af[mt][3], b0, b1);
            }
        }
    };

    auto epiSig = [&](int panel) {  // sc = sigmoid(acc + b); acc = 0
#pragma unroll
        for (int mt = 0; mt < 2; mt++)
#pragma unroll
            for (int nt = 0; nt < 4; nt++)
#pragma unroll
                for (int ci = 0; ci < 4; ci++) {
                    int cc = ncolW + nt * 8 + (tg << 1) + (ci & 1);
                    sc[mt][nt][ci] = fsig(acc[mt][nt][ci] + sB[panel * 128 + cc]);
                    acc[mt][nt][ci] = 0.f;
                }
    };
    auto epiG = [&](int panel) {  // sc (=i) *= tanh(acc + b)  -> c ; acc = 0
#pragma unroll
        for (int mt = 0; mt < 2; mt++)
#pragma unroll
            for (int nt = 0; nt < 4; nt++)
#pragma unroll
                for (int ci = 0; ci < 4; ci++) {
                    int cc = ncolW + nt * 8 + (tg << 1) + (ci & 1);
                    sc[mt][nt][ci] *= ftanh(acc[mt][nt][ci] + sB[panel * 128 + cc]);
                    acc[mt][nt][ci] = 0.f;
                }
    };
    auto epiH = [&](int panel) {  // h = sigmoid(acc+b)*tanh(c) -> sH; acc = 0
#pragma unroll
        for (int mt = 0; mt < 2; mt++)
#pragma unroll
            for (int nt = 0; nt < 4; nt++)
#pragma unroll
                for (int ci = 0; ci < 4; ci++) {
                    int r = mrow + mt * 16 + g + ((ci >> 1) << 3);
                    int cc = ncolW + nt * 8 + (tg << 1) + (ci & 1);
                    float h = fsig(acc[mt][nt][ci] + sB[panel * 128 + cc]) * ftanh(sc[mt][nt][ci]);
                    sH[r * HS + cc] = h;
                    acc[mt][nt][ci] = 0.f;
                }
    };

    // ---------------- 9-chunk pipeline ----------------
    // c0: L0 i
    WAITSYNC(1);
    gemmChunk(sX, XS, 0, sW0);
    __syncthreads();
    prefW(Wih0 + 384 * INP, INP, sW0);  // chunk2: L0 gate-o
    cpcommit();
    epiSig(0);
    // c1: L0 g
    WAITSYNC(1);
    gemmChunk(sX, XS, 0, sW1);
    __syncthreads();
    prefW(Wih1, HID, sW1);  // chunk3: L1 i k0
    cpcommit();
    epiG(1);
    // c2: L0 o -> h0 into sH
    WAITSYNC(1);
    gemmChunk(sX, XS, 0, sW0);
    __syncthreads();
    prefW(Wih1 + 64, HID, sW0);  // chunk4: L1 i k1
    cpcommit();
    epiH(2);
    // c3: L1 i k0
    WAITSYNC(1);
    gemmChunk(sH, HS, 0, sW1);
    __syncthreads();
    prefW(Wih1 + 256 * HID, HID, sW1);  // chunk5: L1 g k0
    cpcommit();
    // c4: L1 i k1
    WAITSYNC(1);
    gemmChunk(sH, HS, 64, sW0);
    __syncthreads();
    prefW(Wih1 + 256 * HID + 64, HID, sW0);  // chunk6: L1 g k1
    cpcommit();
    epiSig(3);
    // c5: L1 g k0
    WAITSYNC(1);
    gemmChunk(sH, HS, 0, sW1);
    __syncthreads();
    prefW(Wih1 + 384 * HID, HID, sW1);  // chunk7: L1 o k0
    cpcommit();
    // c6: L1 g k1
    WAITSYNC(1);
    gemmChunk(sH, HS, 64, sW0);
    __syncthreads();
    prefW(Wih1 + 384 * HID + 64, HID, sW0);  // chunk8: L1 o k1
    cpcommit();
    epiG(4);
    // c7: L1 o k0
    WAITSYNC(1);
    gemmChunk(sH, HS, 0, sW1);
    // c8: L1 o k1
    WAITSYNC(0);
    gemmChunk(sH, HS, 64, sW0);
    __syncthreads();  // every warp done reading h0 before overwriting sH with h1
    epiH(5);          // h1 -> sH
    __syncthreads();

    // ---------------- heads on tensor cores (warps 0..7) ----------------
    float* pol = out;
    float* val = out + (size_t)BATCH * NACT;
    if (wid < 8) {
        float ha[3][4];
#pragma unroll
        for (int nt = 0; nt < 3; nt++)
#pragma unroll
            for (int ci = 0; ci < 4; ci++) ha[nt][ci] = 0.f;
        const unsigned* uA = (const unsigned*)sH;
        const unsigned* uW = (const unsigned*)sWH;
        const int mrowH = wid * 16;
#pragma unroll
        for (int ks = 0; ks < 16; ks++) {
            const unsigned* base = uA + (mrowH + g) * HS + ks * 8 + tg;
            unsigned a0 = base[0], a1 = base[8 * HS], a2 = base[4], a3 = base[8 * HS + 4];
#pragma unroll
            for (int nt = 0; nt < 3; nt++) {
                const unsigned* wb = uW + (nt * 8 + g) * WHS + ks * 8 + tg;
                MMA_TF32(ha[nt], a0, a1, a2, a3, wb[0], wb[4]);
            }
        }
#pragma unroll
        for (int nt = 0; nt < 3; nt++)
#pragma unroll
            for (int ci = 0; ci < 4; ci++) {
                int col = nt * 8 + (tg << 1) + (ci & 1);
                int r = mrowH + g + ((ci >> 1) << 3);
                int gr = rowbase + r;
                if (col < NACT)
                    pol[(size_t)gr * NACT + col] = ha[nt][ci] + bp[col];
                else if (col == NACT)
                    val[gr] = ha[nt][ci] + bv[0];
            }
    }
}

extern "C" void kernel_launch(void* const* d_in, const int* in_sizes, int n_in,
                              void* d_out, int out_size) {
    const float* x    = (const float*)d_in[0];
    const float* Wih0 = (const float*)d_in[1];
    // d_in[2] = Whh0: unused (h=0)
    const float* bih0 = (const float*)d_in[3];
    const float* bhh0 = (const float*)d_in[4];
    const float* Wih1 = (const float*)d_in[5];
    // d_in[6] = Whh1: unused (h=0)
    const float* bih1 = (const float*)d_in[7];
    const float* bhh1 = (const float*)d_in[8];
    const float* Wp   = (const float*)d_in[9];
    const float* bp   = (const float*)d_in[10];
    const float* Wv   = (const float*)d_in[11];
    const float* bv   = (const float*)d_in[12];
    float* out = (float*)d_out;

    cudaFuncSetAttribute(lstm_policy_kernel,
                         cudaFuncAttributeMaxDynamicSharedMemorySize, SMEM_BYTES);

    dim3 grid(BATCH / BM);
    dim3 block(NTHR);
    lstm_policy_kernel<<<grid, block, SMEM_BYTES>>>(
        x, Wih0, bih0, bhh0, Wih1, bih1, bhh1, Wp, bp, Wv, bv, out);
}

// round 6
// speedup vs baseline: 3.0601x; 1.0036x over previous
#include <cuda_runtime.h>
#include <cstdint>

#define BATCH 65536
#define INP 64
#define HID 128
#define NACT 16
#define BM 64
#define NTHR 256

// smem strides (floats); all ≡ 4 (mod 32) -> conflict-free mma fragment loads
// R4 BUG: XS was 36 but the x tile has 64 columns -> corrupted layer-0 A operand.
#define XS 68
#define HS 132
#define WS 36
#define WHS 132

#define SX_OFF 0
#define SH_OFF (BM * XS)                        // 4352
#define SW_OFF (SH_OFF + BM * HS)               // 12800
#define CHUNK_FLOATS (128 * WS)                 // 4608
#define SWH_OFF (SW_OFF + 2 * CHUNK_FLOATS)     // 22016
#define SB_OFF (SWH_OFF + 24 * WHS)             // 25184
#define SMEM_FLOATS (SB_OFF + 6 * 128)          // 25952
#define SMEM_BYTES (SMEM_FLOATS * 4)            // ~101.4 KB -> 2 CTAs/SM (202.8 < 228KB)

__device__ __forceinline__ void cpa16(float* dst, const float* src) {
    unsigned u = (unsigned)__cvta_generic_to_shared(dst);
    asm volatile("cp.async.cg.shared.global [%0], [%1], 16;" ::"r"(u), "l"(src));
}
__device__ __forceinline__ void cpcommit() { asm volatile("cp.async.commit_group;"); }

__device__ __forceinline__ float fsig(float v) {
    float e = __expf(-v);
    return __fdividef(1.f, 1.f + e);
}
__device__ __forceinline__ float ftanh(float v) {
    float e = __expf(2.f * v);
    return __fdividef(e - 1.f, e + 1.f);
}

#define MMA_TF32(d, a0, a1, a2, a3, b0, b1)                                     \
    asm volatile(                                                               \
        "mma.sync.aligned.m16n8k8.row.col.f32.tf32.tf32.f32 "                   \
        "{%0,%1,%2,%3},{%4,%5,%6,%7},{%8,%9},{%0,%1,%2,%3};"                    \
        : "+f"(d[0]), "+f"(d[1]), "+f"(d[2]), "+f"(d[3])                        \
        : "r"(a0), "r"(a1), "r"(a2), "r"(a3), "r"(b0), "r"(b1))

__global__ void __launch_bounds__(NTHR, 2)
lstm_policy_kernel(const float* __restrict__ x,
                   const float* __restrict__ Wih0,
                   const float* __restrict__ bih0,
                   const float* __restrict__ bhh0,
                   const float* __restrict__ Wih1,
                   const float* __restrict__ bih1,
                   const float* __restrict__ bhh1,
                   const float* __restrict__ Wp,
                   const float* __restrict__ bp,
                   const float* __restrict__ Wv,
                   const float* __restrict__ bv,
                   float* __restrict__ out) {
    extern __shared__ float sm[];
    float* sX = sm + SX_OFF;
    float* sH = sm + SH_OFF;
    float* sW0 = sm + SW_OFF;
    float* sW1 = sm + SW_OFF + CHUNK_FLOATS;
    float* sWH = sm + SWH_OFF;
    float* sB = sm + SB_OFF;

    const int tid = threadIdx.x;
    const int wid = tid >> 5, lane = tid & 31;
    const int g = lane >> 2, tg = lane & 3;
    const int mrow = (wid & 1) * 32;   // 2 row-groups of 32 (BM=64)
    const int ncolW = (wid >> 1) * 32; // 4 col-groups of 32
    const int rowbase = blockIdx.x * BM;

    // prefetch weight chunk c (of 18) into buffer dst; chunk = [128 out x 32 K]
    auto prefW = [&](int c, float* dst) {
        const float* src;
        int ld;
        if (c < 6) {  // L0: gate = c/2, K-half = c&1
            int gate = c >> 1;
            int gbase = (gate == 0) ? 0 : (gate == 1 ? 256 : 384);
            src = Wih0 + (size_t)gbase * INP + ((c & 1) << 5);
            ld = INP;
        } else {  // L1: gate = (c-6)/4, K-quarter = (c-6)&3
            int cc = c - 6;
            int gate = cc >> 2;
            int gbase = (gate == 0) ? 0 : (gate == 1 ? 256 : 384);
            src = Wih1 + (size_t)gbase * HID + ((cc & 3) << 5);
            ld = HID;
        }
#pragma unroll
        for (int i = 0; i < 4; i++) {
            int idx = tid + i * NTHR;  // 1024 float4
            int r = idx >> 3;          // 8 float4 per 32-col row
            int c4 = idx & 7;
            cpa16(dst + r * WS + c4 * 4, src + (size_t)r * ld + c4 * 4);
        }
    };

    // ---- prologue: group0 = x + head weights + chunk0 ; group1 = chunk1 ----
    {
        const float* xs = x + (size_t)rowbase * INP;
#pragma unroll
        for (int i = 0; i < 4; i++) {
            int idx = tid + i * NTHR;  // 1024 float4 (64 rows x 16)
            int r = idx >> 4;
            int c4 = idx & 15;
            cpa16(sX + r * XS + c4 * 4, xs + r * INP + c4 * 4);
        }
        // 17 rows x 32 float4 = 544 > NTHR: strided loop (R2 lesson)
#pragma unroll
        for (int idx = tid; idx < 544; idx += NTHR) {
            int r = idx >> 5, c4 = idx & 31;
            const float* srcp = (r < 16) ? (Wp + r * HID + c4 * 4) : (Wv + c4 * 4);
            cpa16(sWH + r * WHS + c4 * 4, srcp);
        }
        prefW(0, sW0);
        cpcommit();
        prefW(1, sW1);
        cpcommit();
    }

    // combined biases + zero-pad head rows 17..23 (plain stores; barriers below cover)
    if (tid < 128) {
        sB[tid] = bih0[tid] + bhh0[tid];
        sB[128 + tid] = bih0[256 + tid] + bhh0[256 + tid];
        sB[256 + tid] = bih0[384 + tid] + bhh0[384 + tid];
        sB[384 + tid] = bih1[tid] + bhh1[tid];
        sB[512 + tid] = bih1[256 + tid] + bhh1[256 + tid];
        sB[640 + tid] = bih1[384 + tid] + bhh1[384 + tid];
    }
#pragma unroll
    for (int idx = tid; idx < 7 * HID; idx += NTHR) {
        int r = 17 + idx / HID, c = idx % HID;
        sWH[r * WHS + c] = 0.f;
    }

    float acc[2][4][4], sc[2][4][4];
#pragma unroll
    for (int mt = 0; mt < 2; mt++)
#pragma unroll
        for (int nt = 0; nt < 4; nt++)
#pragma unroll
            for (int ci = 0; ci < 4; ci++) acc[mt][nt][ci] = 0.f;

    // one K=32 gemm chunk into acc; warp tile 32x32
    auto gemmChunk = [&](const float* A, int AS_, int koffA, const float* Wbuf) {
        const unsigned* uA = (const unsigned*)A;
        const unsigned* uW = (const unsigned*)Wbuf;
#pragma unroll
        for (int ks = 0; ks < 4; ks++) {
            unsigned af[2][4];
#pragma unroll
            for (int mt = 0; mt < 2; mt++) {
                const unsigned* base = uA + (mrow + mt * 16 + g) * AS_ + koffA + ks * 8 + tg;
                af[mt][0] = base[0];
                af[mt][1] = base[8 * AS_];
                af[mt][2] = base[4];
                af[mt][3] = base[8 * AS_ + 4];
            }
#pragma unroll
            for (int nt = 0; nt < 4; nt++) {
                const unsigned* wb = uW + (ncolW + nt * 8 + g) * WS + ks * 8 + tg;
                unsigned b0 = wb[0], b1 = wb[4];
#pragma unroll
                for (int mt = 0; mt < 2; mt++)
                    MMA_TF32(acc[mt][nt], af[mt][0], af[mt][1], af[mt][2], af[mt][3], b0, b1);
            }
        }
    };

    auto epiSig = [&](int panel) {  // sc = sigmoid(acc + b); acc = 0
#pragma unroll
        for (int mt = 0; mt < 2; mt++)
#pragma unroll
            for (int nt = 0; nt < 4; nt++)
#pragma unroll
                for (int ci = 0; ci < 4; ci++) {
                    int cc = ncolW + nt * 8 + (tg << 1) + (ci & 1);
                    sc[mt][nt][ci] = fsig(acc[mt][nt][ci] + sB[panel * 128 + cc]);
                    acc[mt][nt][ci] = 0.f;
                }
    };
    auto epiG = [&](int panel) {  // sc (=i) *= tanh(acc + b) -> c ; acc = 0
#pragma unroll
        for (int mt = 0; mt < 2; mt++)
#pragma unroll
            for (int nt = 0; nt < 4; nt++)
#pragma unroll
                for (int ci = 0; ci < 4; ci++) {
                    int cc = ncolW + nt * 8 + (tg << 1) + (ci & 1);
                    sc[mt][nt][ci] *= ftanh(acc[mt][nt][ci] + sB[panel * 128 + cc]);
                    acc[mt][nt][ci] = 0.f;
                }
    };
    auto epiH = [&](int panel) {  // h = sigmoid(acc+b)*tanh(c) -> sH; acc = 0
#pragma unroll
        for (int mt = 0; mt < 2; mt++)
#pragma unroll
            for (int nt = 0; nt < 4; nt++)
#pragma unroll
                for (int ci = 0; ci < 4; ci++) {
                    int r = mrow + mt * 16 + g + ((ci >> 1) << 3);
                    int cc = ncolW + nt * 8 + (tg << 1) + (ci & 1);
                    float h = fsig(acc[mt][nt][ci] + sB[panel * 128 + cc]) * ftanh(sc[mt][nt][ci]);
                    sH[r * HS + cc] = h;
                    acc[mt][nt][ci] = 0.f;
                }
    };

    // ---------------- 18-chunk rolled pipeline ----------------
    // chunk c lives in buffer (c&1); one group committed per iteration
#pragma unroll 2
    for (int c = 0; c < 18; ++c) {
        asm volatile("cp.async.wait_group 1;");
        __syncthreads();  // chunk c ready (and for c==6: h0 writes visible)

        if (c < 6)
            gemmChunk(sX, XS, (c & 1) * 32, (c & 1) ? sW1 : sW0);
        else
            gemmChunk(sH, HS, ((c - 6) & 3) * 32, (c & 1) ? sW1 : sW0);

        __syncthreads();  // all warps done reading buffer (c&1)
        if (c + 2 < 18) prefW(c + 2, (c & 1) ? sW1 : sW0);
        cpcommit();  // exactly one group per iteration (may be empty)

        if (c == 1) epiSig(0);
        else if (c == 3) epiG(1);
        else if (c == 5) epiH(2);   // h0 -> sH (read from c==6 after next barrier)
        else if (c == 9) epiSig(3);
        else if (c == 13) epiG(4);
    }
    // post-gemm sync of c==17 already passed: all warps done reading h0
    epiH(5);  // h1 -> sH
    __syncthreads();

    // ---------------- heads on tensor cores (warps 0..3) ----------------
    float* pol = out;
    float* val = out + (size_t)BATCH * NACT;
    if (wid < 4) {
        float ha[3][4];
#pragma unroll
        for (int nt = 0; nt < 3; nt++)
#pragma unroll
            for (int ci = 0; ci < 4; ci++) ha[nt][ci] = 0.f;
        const unsigned* uA = (const unsigned*)sH;
        const unsigned* uW = (const unsigned*)sWH;
        const int mrowH = wid * 16;
#pragma unroll
        for (int ks = 0; ks < 16; ks++) {
            const unsigned* base = uA + (mrowH + g) * HS + ks * 8 + tg;
            unsigned a0 = base[0], a1 = base[8 * HS], a2 = base[4], a3 = base[8 * HS + 4];
#pragma unroll
            for (int nt = 0; nt < 3; nt++) {
                const unsigned* wb = uW + (nt * 8 + g) * WHS + ks * 8 + tg;
                MMA_TF32(ha[nt], a0, a1, a2, a3, wb[0], wb[4]);
            }
        }
#pragma unroll
        for (int nt = 0; nt < 3; nt++)
#pragma unroll
            for (int ci = 0; ci < 4; ci++) {
                int col = nt * 8 + (tg << 1) + (ci & 1);
                int r = mrowH + g + ((ci >> 1) << 3);
                int gr = rowbase + r;
                if (col < NACT)
                    pol[(size_t)gr * NACT + col] = ha[nt][ci] + bp[col];
                else if (col == NACT)
                    val[gr] = ha[nt][ci] + bv[0];
            }
    }
}

extern "C" void kernel_launch(void* const* d_in, const int* in_sizes, int n_in,
                              void* d_out, int out_size) {
    const float* x    = (const float*)d_in[0];
    const float* Wih0 = (const float*)d_in[1];
    // d_in[2] = Whh0: unused (h=0)
    const float* bih0 = (const float*)d_in[3];
    const float* bhh0 = (const float*)d_in[4];
    const float* Wih1 = (const float*)d_in[5];
    // d_in[6] = Whh1: unused (h=0)
    const float* bih1 = (const float*)d_in[7];
    const float* bhh1 = (const float*)d_in[8];
    const float* Wp   = (const float*)d_in[9];
    const float* bp   = (const float*)d_in[10];
    const float* Wv   = (const float*)d_in[11];
    const float* bv   = (const float*)d_in[12];
    float* out = (float*)d_out;

    cudaFuncSetAttribute(lstm_policy_kernel,
                         cudaFuncAttributeMaxDynamicSharedMemorySize, SMEM_BYTES);

    dim3 grid(BATCH / BM);
    dim3 block(NTHR);
    lstm_policy_kernel<<<grid, block, SMEM_BYTES>>>(
        x, Wih0, bih0, bhh0, Wih1, bih1, bhh1, Wp, bp, Wv, bv, out);
}

// round 7
// speedup vs baseline: 3.7324x; 1.2197x over previous
#include <cuda_runtime.h>
#include <cstdint>

#define BATCH 65536
#define INP 64
#define HID 128
#define NACT 16
#define BM 64
#define NTHR 256

// smem strides (floats); all ≡ 4 (mod 32) -> conflict-free LDSM row addressing
#define XS 68
#define HS 132
#define WS 36
#define WHS 132

// Layout (floats): sH [64x132] at 0 (sX [64x68] ALIASED under it; x dead after chunk 5),
// then 3-buffer weight ring, head weights, biases.
#define SW_OFF 8448
#define CHUNK_FLOATS (128 * WS)                  // 4608
#define SWH_OFF (SW_OFF + 3 * CHUNK_FLOATS)      // 22272
#define SB_OFF (SWH_OFF + 24 * WHS)              // 25440
#define SMEM_FLOATS (SB_OFF + 6 * 128)           // 26208
#define SMEM_BYTES (SMEM_FLOATS * 4)             // 104832 B -> 2 CTAs/SM (209.7KB < 228KB)

__device__ __forceinline__ void cpa16(float* dst, const float* src) {
    unsigned u = (unsigned)__cvta_generic_to_shared(dst);
    asm volatile("cp.async.cg.shared.global [%0], [%1], 16;" ::"r"(u), "l"(src));
}
__device__ __forceinline__ void cpcommit() { asm volatile("cp.async.commit_group;"); }

__device__ __forceinline__ float fsig(float v) {
    float e = __expf(-v);
    return __fdividef(1.f, 1.f + e);
}
__device__ __forceinline__ float ftanh(float v) {
    float e = __expf(2.f * v);
    return __fdividef(e - 1.f, e + 1.f);
}

#define MMA_TF32(d, a0, a1, a2, a3, b0, b1)                                     \
    asm volatile(                                                               \
        "mma.sync.aligned.m16n8k8.row.col.f32.tf32.tf32.f32 "                   \
        "{%0,%1,%2,%3},{%4,%5,%6,%7},{%8,%9},{%0,%1,%2,%3};"                    \
        : "+f"(d[0]), "+f"(d[1]), "+f"(d[2]), "+f"(d[3])                        \
        : "r"(a0), "r"(a1), "r"(a2), "r"(a3), "r"(b0), "r"(b1))

__device__ __forceinline__ void ldsm4(unsigned r[4], unsigned addr) {
    asm volatile("ldmatrix.sync.aligned.m8n8.x4.shared.b16 {%0,%1,%2,%3}, [%4];"
                 : "=r"(r[0]), "=r"(r[1]), "=r"(r[2]), "=r"(r[3])
                 : "r"(addr));
}

__global__ void __launch_bounds__(NTHR, 2)
lstm_policy_kernel(const float* __restrict__ x,
                   const float* __restrict__ Wih0,
                   const float* __restrict__ bih0,
                   const float* __restrict__ bhh0,
                   const float* __restrict__ Wih1,
                   const float* __restrict__ bih1,
                   const float* __restrict__ bhh1,
                   const float* __restrict__ Wp,
                   const float* __restrict__ bp,
                   const float* __restrict__ Wv,
                   const float* __restrict__ bv,
                   float* __restrict__ out) {
    extern __shared__ float sm[];
    float* sH = sm;          // [64][132] h0 then h1
    float* sX = sm;          // [64][68]  x tile, ALIASED (dead after chunk 5)
    float* sW = sm + SW_OFF; // 3 x [128][36] weight ring
    float* sWH = sm + SWH_OFF;
    float* sB = sm + SB_OFF;

    const int tid = threadIdx.x;
    const int wid = tid >> 5, lane = tid & 31;
    const int g = lane >> 2, tg = lane & 3;
    const int mrow = (wid & 1) * 32;
    const int ncolW = (wid >> 1) * 32;
    const int rowbase = blockIdx.x * BM;

    // prefetch weight chunk c (of 18) into buffer dst; chunk = [128 out x 32 K]
    auto prefW = [&](int c, float* dst) {
        const float* src;
        int ld;
        if (c < 6) {
            int gate = c >> 1;
            int gbase = (gate == 0) ? 0 : (gate == 1 ? 256 : 384);
            src = Wih0 + (size_t)gbase * INP + ((c & 1) << 5);
            ld = INP;
        } else {
            int cc = c - 6;
            int gate = cc >> 2;
            int gbase = (gate == 0) ? 0 : (gate == 1 ? 256 : 384);
            src = Wih1 + (size_t)gbase * HID + ((cc & 3) << 5);
            ld = HID;
        }
#pragma unroll
        for (int i = 0; i < 4; i++) {
            int idx = tid + i * NTHR;
            int r = idx >> 3;
            int c4 = idx & 7;
            cpa16(dst + r * WS + c4 * 4, src + (size_t)r * ld + c4 * 4);
        }
    };

    // ---- prologue: g0 = {x, head weights, chunk0}; g1 = {chunk1} ----
    {
        const float* xs = x + (size_t)rowbase * INP;
#pragma unroll
        for (int i = 0; i < 4; i++) {
            int idx = tid + i * NTHR;
            int r = idx >> 4;
            int c4 = idx & 15;
            cpa16(sX + r * XS + c4 * 4, xs + r * INP + c4 * 4);
        }
#pragma unroll
        for (int idx = tid; idx < 544; idx += NTHR) {  // strided: 544 > NTHR
            int r = idx >> 5, c4 = idx & 31;
            const float* srcp = (r < 16) ? (Wp + r * HID + c4 * 4) : (Wv + c4 * 4);
            cpa16(sWH + r * WHS + c4 * 4, srcp);
        }
        prefW(0, sW);
        cpcommit();
        prefW(1, sW + CHUNK_FLOATS);
        cpcommit();
    }

    // combined biases + zero-pad head rows 17..23
    if (tid < 128) {
        sB[tid] = bih0[tid] + bhh0[tid];
        sB[128 + tid] = bih0[256 + tid] + bhh0[256 + tid];
        sB[256 + tid] = bih0[384 + tid] + bhh0[384 + tid];
        sB[384 + tid] = bih1[tid] + bhh1[tid];
        sB[512 + tid] = bih1[256 + tid] + bhh1[256 + tid];
        sB[640 + tid] = bih1[384 + tid] + bhh1[384 + tid];
    }
#pragma unroll
    for (int idx = tid; idx < 7 * HID; idx += NTHR) {
        int r = 17 + idx / HID, c = idx % HID;
        sWH[r * WHS + c] = 0.f;
    }

    // ---- LDSM address precompute (verified vs passing scalar-LDS mapping) ----
    // A tiles: t0 rows+0/col+0, t1 rows+8/col+0, t2 rows+0/col+4, t3 rows+8/col+4
    // B tiles (per nt-pair): t0 nt b0, t1 nt b1, t2 nt+1 b0, t3 nt+1 b1
    const int j8 = lane & 7, sel = lane >> 3;
    const int arow = ((sel & 1) << 3) + j8;
    const int acol = (sel >> 1) << 2;
    const unsigned shBase = (unsigned)__cvta_generic_to_shared(sm);
    const unsigned swBase = shBase + SW_OFF * 4;
    const unsigned aX0 = shBase + ((mrow + arow) * XS + acol) * 4;
    const unsigned aX1 = shBase + ((mrow + 16 + arow) * XS + acol) * 4;
    const unsigned aH0 = shBase + ((mrow + arow) * HS + acol) * 4;
    const unsigned aH1 = shBase + ((mrow + 16 + arow) * HS + acol) * 4;
    const unsigned bO0 = ((ncolW + (sel >> 1) * 8 + j8) * WS + ((sel & 1) << 2)) * 4;
    const unsigned bO1 = ((ncolW + (2 + (sel >> 1)) * 8 + j8) * WS + ((sel & 1) << 2)) * 4;

    float acc[2][4][4], sc[2][4][4];
#pragma unroll
    for (int mt = 0; mt < 2; mt++)
#pragma unroll
        for (int nt = 0; nt < 4; nt++)
#pragma unroll
            for (int ci = 0; ci < 4; ci++) acc[mt][nt][ci] = 0.f;

    // one K=32 gemm chunk: 16 LDSM.x4 + 32 MMA (was 64 LDS.32 + 32 MMA)
    auto gemmChunk = [&](unsigned a0addr, unsigned a1addr, unsigned wbase) {
#pragma unroll
        for (int ks = 0; ks < 4; ks++) {
            unsigned af0[4], af1[4], bf0[4], bf1[4];
            ldsm4(af0, a0addr + ks * 32);
            ldsm4(af1, a1addr + ks * 32);
            ldsm4(bf0, wbase + bO0 + ks * 32);
            ldsm4(bf1, wbase + bO1 + ks * 32);
            MMA_TF32(acc[0][0], af0[0], af0[1], af0[2], af0[3], bf0[0], bf0[1]);
            MMA_TF32(acc[1][0], af1[0], af1[1], af1[2], af1[3], bf0[0], bf0[1]);
            MMA_TF32(acc[0][1], af0[0], af0[1], af0[2], af0[3], bf0[2], bf0[3]);
            MMA_TF32(acc[1][1], af1[0], af1[1], af1[2], af1[3], bf0[2], bf0[3]);
            MMA_TF32(acc[0][2], af0[0], af0[1], af0[2], af0[3], bf1[0], bf1[1]);
            MMA_TF32(acc[1][2], af1[0], af1[1], af1[2], af1[3], bf1[0], bf1[1]);
            MMA_TF32(acc[0][3], af0[0], af0[1], af0[2], af0[3], bf1[2], bf1[3]);
            MMA_TF32(acc[1][3], af1[0], af1[1], af1[2], af1[3], bf1[2], bf1[3]);
        }
    };

    auto epiSig = [&](int panel) {
#pragma unroll
        for (int mt = 0; mt < 2; mt++)
#pragma unroll
            for (int nt = 0; nt < 4; nt++)
#pragma unroll
                for (int ci = 0; ci < 4; ci++) {
                    int cc = ncolW + nt * 8 + (tg << 1) + (ci & 1);
                    sc[mt][nt][ci] = fsig(acc[mt][nt][ci] + sB[panel * 128 + cc]);
                    acc[mt][nt][ci] = 0.f;
                }
    };
    auto epiG = [&](int panel) {
#pragma unroll
        for (int mt = 0; mt < 2; mt++)
#pragma unroll
            for (int nt = 0; nt < 4; nt++)
#pragma unroll
                for (int ci = 0; ci < 4; ci++) {
                    int cc = ncolW + nt * 8 + (tg << 1) + (ci & 1);
                    sc[mt][nt][ci] *= ftanh(acc[mt][nt][ci] + sB[panel * 128 + cc]);
                    acc[mt][nt][ci] = 0.f;
                }
    };
    auto epiH = [&](int panel) {
#pragma unroll
        for (int mt = 0; mt < 2; mt++)
#pragma unroll
            for (int nt = 0; nt < 4; nt++)
#pragma unroll
                for (int ci = 0; ci < 4; ci++) {
                    int r = mrow + mt * 16 + g + ((ci >> 1) << 3);
                    int cc = ncolW + nt * 8 + (tg << 1) + (ci & 1);
                    float h = fsig(acc[mt][nt][ci] + sB[panel * 128 + cc]) * ftanh(sc[mt][nt][ci]);
                    sH[r * HS + cc] = h;
                    acc[mt][nt][ci] = 0.f;
                }
    };

    // ring state: w0 = buffer holding current chunk c; one sync per iteration.
    unsigned w0 = swBase, w1 = swBase + CHUNK_FLOATS * 4, w2 = swBase + 2 * CHUNK_FLOATS * 4;
    float *p0 = sW, *p1 = sW + CHUNK_FLOATS, *p2 = sW + 2 * CHUNK_FLOATS;

    // ---- L0: chunks 0..5 read sX ----
#pragma unroll
    for (int c = 0; c < 6; ++c) {
        asm volatile("cp.async.wait_group 1;");
        __syncthreads();  // chunk c ready; all threads done with gemm(c-1)
        gemmChunk(aX0 + (c & 1) * 128, aX1 + (c & 1) * 128, w0);
        prefW(c + 2, p2);  // buf last read at iter c-1: safe after this iter's sync
        cpcommit();
        if (c == 1) epiSig(0);
        else if (c == 3) epiG(1);
        {
            unsigned t = w0; w0 = w1; w1 = w2; w2 = t;
            float* q = p0; p0 = p1; p1 = p2; p2 = q;
        }
    }

    // ---- chunk 6: h0 overwrites the aliased sX region -> extra barrier ----
    asm volatile("cp.async.wait_group 1;");
    __syncthreads();  // all done reading sX (gemm 5)
    epiH(2);          // h0 -> sH (clobbers sX region)
    __syncthreads();  // h0 visible to all warps
    gemmChunk(aH0, aH1, w0);
    prefW(8, p2);
    cpcommit();
    {
        unsigned t = w0; w0 = w1; w1 = w2; w2 = t;
        float* q = p0; p0 = p1; p1 = p2; p2 = q;
    }

    // ---- L1: chunks 7..17 read sH ----
#pragma unroll 1
    for (int c = 7; c < 18; ++c) {
        asm volatile("cp.async.wait_group 1;");
        __syncthreads();
        gemmChunk(aH0 + ((c - 6) & 3) * 128, aH1 + ((c - 6) & 3) * 128, w0);
        if (c < 16) prefW(c + 2, p2);
        cpcommit();
        if (c == 9) epiSig(3);
        else if (c == 13) epiG(4);
        {
            unsigned t = w0; w0 = w1; w1 = w2; w2 = t;
            float* q = p0; p0 = p1; p1 = p2; p2 = q;
        }
    }

    __syncthreads();  // all warps done reading h0 (gemm 17)
    epiH(5);          // h1 -> sH
    __syncthreads();

    // ---- heads on tensor cores (warps 0..3) ----
    float* pol = out;
    float* val = out + (size_t)BATCH * NACT;
    if (wid < 4) {
        float ha[3][4];
#pragma unroll
        for (int nt = 0; nt < 3; nt++)
#pragma unroll
            for (int ci = 0; ci < 4; ci++) ha[nt][ci] = 0.f;
        const unsigned* uA = (const unsigned*)sH;
        const unsigned* uW = (const unsigned*)sWH;
        const int mrowH = wid * 16;
#pragma unroll
        for (int ks = 0; ks < 16; ks++) {
            const unsigned* base = uA + (mrowH + g) * HS + ks * 8 + tg;
            unsigned a0 = base[0], a1 = base[8 * HS], a2 = base[4], a3 = base[8 * HS + 4];
#pragma unroll
            for (int nt = 0; nt < 3; nt++) {
                const unsigned* wb = uW + (nt * 8 + g) * WHS + ks * 8 + tg;
                MMA_TF32(ha[nt], a0, a1, a2, a3, wb[0], wb[4]);
            }
        }
#pragma unroll
        for (int nt = 0; nt < 3; nt++)
#pragma unroll
            for (int ci = 0; ci < 4; ci++) {
                int col = nt * 8 + (tg << 1) + (ci & 1);
                int r = mrowH + g + ((ci >> 1) << 3);
                int gr = rowbase + r;
                if (col < NACT)
                    pol[(size_t)gr * NACT + col] = ha[nt][ci] + bp[col];
                else if (col == NACT)
                    val[gr] = ha[nt][ci] + bv[0];
            }
    }
}

extern "C" void kernel_launch(void* const* d_in, const int* in_sizes, int n_in,
                              void* d_out, int out_size) {
    const float* x    = (const float*)d_in[0];
    const float* Wih0 = (const float*)d_in[1];
    // d_in[2] = Whh0: unused (h=0)
    const float* bih0 = (const float*)d_in[3];
    const float* bhh0 = (const float*)d_in[4];
    const float* Wih1 = (const float*)d_in[5];
    // d_in[6] = Whh1: unused (h=0)
    const float* bih1 = (const float*)d_in[7];
    const float* bhh1 = (const float*)d_in[8];
    const float* Wp   = (const float*)d_in[9];
    const float* bp   = (const float*)d_in[10];
    const float* Wv   = (const float*)d_in[11];
    const float* bv   = (const float*)d_in[12];
    float* out = (float*)d_out;

    cudaFuncSetAttribute(lstm_policy_kernel,
                         cudaFuncAttributeMaxDynamicSharedMemorySize, SMEM_BYTES);

    dim3 grid(BATCH / BM);
    dim3 block(NTHR);
    lstm_policy_kernel<<<grid, block, SMEM_BYTES>>>(
        x, Wih0, bih0, bhh0, Wih1, bih1, bhh1, Wp, bp, Wv, bv, out);
}

// round 8
// speedup vs baseline: 4.0573x; 1.0871x over previous
#include <cuda_runtime.h>
#include <cstdint>

#define BATCH 65536
#define INP 64
#define HID 128
#define NACT 16
#define BM 64
#define NTHR 256

// smem strides (floats); all ≡ 4 (mod 32) -> conflict-free LDSM row addressing
#define XS 68
#define HS 132
#define WS 36
#define WHS 132

// Layout (floats): sH [64x132] at 0 (sX [64x68] ALIASED under it; x dead after chunk 5),
// then 3-buffer weight ring, head weights, biases.
#define SW_OFF 8448
#define CHUNK_FLOATS (128 * WS)                  // 4608
#define SWH_OFF (SW_OFF + 3 * CHUNK_FLOATS)      // 22272
#define SB_OFF (SWH_OFF + 24 * WHS)              // 25440
#define SMEM_FLOATS (SB_OFF + 6 * 128)           // 26208
#define SMEM_BYTES (SMEM_FLOATS * 4)             // 104832 B -> 2 CTAs/SM (209.7KB < 228KB)

__device__ __forceinline__ void cpa16(float* dst, const float* src) {
    unsigned u = (unsigned)__cvta_generic_to_shared(dst);
    asm volatile("cp.async.cg.shared.global [%0], [%1], 16;" ::"r"(u), "l"(src));
}
__device__ __forceinline__ void cpcommit() { asm volatile("cp.async.commit_group;"); }

// HW tanh (MUFU.TANH): 1 MUFU op instead of EX2+RCP chains.
__device__ __forceinline__ float htanh(float v) {
    float r;
    asm("tanh.approx.f32 %0, %1;" : "=f"(r) : "f"(v));
    return r;
}
__device__ __forceinline__ float fsig(float v) {
    return fmaf(htanh(0.5f * v), 0.5f, 0.5f);  // sig(v) = 0.5 + 0.5*tanh(v/2)
}
__device__ __forceinline__ float ftanh(float v) { return htanh(v); }

#define MMA_TF32(d, a0, a1, a2, a3, b0, b1)                                     \
    asm volatile(                                                               \
        "mma.sync.aligned.m16n8k8.row.col.f32.tf32.tf32.f32 "                   \
        "{%0,%1,%2,%3},{%4,%5,%6,%7},{%8,%9},{%0,%1,%2,%3};"                    \
        : "+f"(d[0]), "+f"(d[1]), "+f"(d[2]), "+f"(d[3])                        \
        : "r"(a0), "r"(a1), "r"(a2), "r"(a3), "r"(b0), "r"(b1))

__device__ __forceinline__ void ldsm4(unsigned r[4], unsigned addr) {
    asm volatile("ldmatrix.sync.aligned.m8n8.x4.shared.b16 {%0,%1,%2,%3}, [%4];"
                 : "=r"(r[0]), "=r"(r[1]), "=r"(r[2]), "=r"(r[3])
                 : "r"(addr));
}

__global__ void __launch_bounds__(NTHR, 2)
lstm_policy_kernel(const float* __restrict__ x,
                   const float* __restrict__ Wih0,
                   const float* __restrict__ bih0,
                   const float* __restrict__ bhh0,
                   const float* __restrict__ Wih1,
                   const float* __restrict__ bih1,
                   const float* __restrict__ bhh1,
                   const float* __restrict__ Wp,
                   const float* __restrict__ bp,
                   const float* __restrict__ Wv,
                   const float* __restrict__ bv,
                   float* __restrict__ out) {
    extern __shared__ float sm[];
    float* sH = sm;          // [64][132] h0 then h1
    float* sX = sm;          // [64][68]  x tile, ALIASED (dead after chunk 5)
    float* sW = sm + SW_OFF; // 3 x [128][36] weight ring
    float* sWH = sm + SWH_OFF;
    float* sB = sm + SB_OFF;

    const int tid = threadIdx.x;
    const int wid = tid >> 5, lane = tid & 31;
    const int g = lane >> 2, tg = lane & 3;
    const int mrow = (wid & 1) * 32;
    const int ncolW = (wid >> 1) * 32;
    const int rowbase = blockIdx.x * BM;

    // prefetch weight chunk c (of 18) into buffer dst; chunk = [128 out x 32 K]
    auto prefW = [&](int c, float* dst) {
        const float* src;
        int ld;
        if (c < 6) {
            int gate = c >> 1;
            int gbase = (gate == 0) ? 0 : (gate == 1 ? 256 : 384);
            src = Wih0 + (size_t)gbase * INP + ((c & 1) << 5);
            ld = INP;
        } else {
            int cc = c - 6;
            int gate = cc >> 2;
            int gbase = (gate == 0) ? 0 : (gate == 1 ? 256 : 384);
            src = Wih1 + (size_t)gbase * HID + ((cc & 3) << 5);
            ld = HID;
        }
#pragma unroll
        for (int i = 0; i < 4; i++) {
            int idx = tid + i * NTHR;
            int r = idx >> 3;
            int c4 = idx & 7;
            cpa16(dst + r * WS + c4 * 4, src + (size_t)r * ld + c4 * 4);
        }
    };

    // ---- prologue: g0 = {x, head weights, chunk0}; g1 = {chunk1} ----
    {
        const float* xs = x + (size_t)rowbase * INP;
#pragma unroll
        for (int i = 0; i < 4; i++) {
            int idx = tid + i * NTHR;
            int r = idx >> 4;
            int c4 = idx & 15;
            cpa16(sX + r * XS + c4 * 4, xs + r * INP + c4 * 4);
        }
#pragma unroll
        for (int idx = tid; idx < 544; idx += NTHR) {  // strided: 544 > NTHR
            int r = idx >> 5, c4 = idx & 31;
            const float* srcp = (r < 16) ? (Wp + r * HID + c4 * 4) : (Wv + c4 * 4);
            cpa16(sWH + r * WHS + c4 * 4, srcp);
        }
        prefW(0, sW);
        cpcommit();
        prefW(1, sW + CHUNK_FLOATS);
        cpcommit();
    }

    // combined biases + zero-pad head rows 17..23
    if (tid < 128) {
        sB[tid] = bih0[tid] + bhh0[tid];
        sB[128 + tid] = bih0[256 + tid] + bhh0[256 + tid];
        sB[256 + tid] = bih0[384 + tid] + bhh0[384 + tid];
        sB[384 + tid] = bih1[tid] + bhh1[tid];
        sB[512 + tid] = bih1[256 + tid] + bhh1[256 + tid];
        sB[640 + tid] = bih1[384 + tid] + bhh1[384 + tid];
    }
#pragma unroll
    for (int idx = tid; idx < 7 * HID; idx += NTHR) {
        int r = 17 + idx / HID, c = idx % HID;
        sWH[r * WHS + c] = 0.f;
    }

    // ---- LDSM address precompute (same mapping as passing R7) ----
    const int j8 = lane & 7, sel = lane >> 3;
    const int arow = ((sel & 1) << 3) + j8;
    const int acol = (sel >> 1) << 2;
    const unsigned shBase = (unsigned)__cvta_generic_to_shared(sm);
    const unsigned swBase = shBase + SW_OFF * 4;
    const unsigned aX0 = shBase + ((mrow + arow) * XS + acol) * 4;
    const unsigned aX1 = shBase + ((mrow + 16 + arow) * XS + acol) * 4;
    const unsigned aH0 = shBase + ((mrow + arow) * HS + acol) * 4;
    const unsigned aH1 = shBase + ((mrow + 16 + arow) * HS + acol) * 4;
    const unsigned bO0 = ((ncolW + (sel >> 1) * 8 + j8) * WS + ((sel & 1) << 2)) * 4;
    const unsigned bO1 = ((ncolW + (2 + (sel >> 1)) * 8 + j8) * WS + ((sel & 1) << 2)) * 4;

    float acc[2][4][4], sc[2][4][4];
#pragma unroll
    for (int mt = 0; mt < 2; mt++)
#pragma unroll
        for (int nt = 0; nt < 4; nt++)
#pragma unroll
            for (int ci = 0; ci < 4; ci++) acc[mt][nt][ci] = 0.f;

    // one K=32 gemm chunk: 16 LDSM.x4 + 32 MMA
    auto gemmChunk = [&](unsigned a0addr, unsigned a1addr, unsigned wbase) {
#pragma unroll
        for (int ks = 0; ks < 4; ks++) {
            unsigned af0[4], af1[4], bf0[4], bf1[4];
            ldsm4(af0, a0addr + ks * 32);
            ldsm4(af1, a1addr + ks * 32);
            ldsm4(bf0, wbase + bO0 + ks * 32);
            ldsm4(bf1, wbase + bO1 + ks * 32);
            MMA_TF32(acc[0][0], af0[0], af0[1], af0[2], af0[3], bf0[0], bf0[1]);
            MMA_TF32(acc[1][0], af1[0], af1[1], af1[2], af1[3], bf0[0], bf0[1]);
            MMA_TF32(acc[0][1], af0[0], af0[1], af0[2], af0[3], bf0[2], bf0[3]);
            MMA_TF32(acc[1][1], af1[0], af1[1], af1[2], af1[3], bf0[2], bf0[3]);
            MMA_TF32(acc[0][2], af0[0], af0[1], af0[2], af0[3], bf1[0], bf1[1]);
            MMA_TF32(acc[1][2], af1[0], af1[1], af1[2], af1[3], bf1[0], bf1[1]);
            MMA_TF32(acc[0][3], af0[0], af0[1], af0[2], af0[3], bf1[2], bf1[3]);
            MMA_TF32(acc[1][3], af1[0], af1[1], af1[2], af1[3], bf1[2], bf1[3]);
        }
    };

    auto epiSig = [&](int panel) {
#pragma unroll
        for (int mt = 0; mt < 2; mt++)
#pragma unroll
            for (int nt = 0; nt < 4; nt++)
#pragma unroll
                for (int ci = 0; ci < 4; ci++) {
                    int cc = ncolW + nt * 8 + (tg << 1) + (ci & 1);
                    sc[mt][nt][ci] = fsig(acc[mt][nt][ci] + sB[panel * 128 + cc]);
                    acc[mt][nt][ci] = 0.f;
                }
    };
    auto epiG = [&](int panel) {
#pragma unroll
        for (int mt = 0; mt < 2; mt++)
#pragma unroll
            for (int nt = 0; nt < 4; nt++)
#pragma unroll
                for (int ci = 0; ci < 4; ci++) {
                    int cc = ncolW + nt * 8 + (tg << 1) + (ci & 1);
                    sc[mt][nt][ci] *= ftanh(acc[mt][nt][ci] + sB[panel * 128 + cc]);
                    acc[mt][nt][ci] = 0.f;
                }
    };
    auto epiH = [&](int panel) {
#pragma unroll
        for (int mt = 0; mt < 2; mt++)
#pragma unroll
            for (int nt = 0; nt < 4; nt++)
#pragma unroll
                for (int ci = 0; ci < 4; ci++) {
                    int r = mrow + mt * 16 + g + ((ci >> 1) << 3);
                    int cc = ncolW + nt * 8 + (tg << 1) + (ci & 1);
                    float h = fsig(acc[mt][nt][ci] + sB[panel * 128 + cc]) * ftanh(sc[mt][nt][ci]);
                    sH[r * HS + cc] = h;
                    acc[mt][nt][ci] = 0.f;
                }
    };

    // ring state: w0 = buffer holding current chunk c
    unsigned w0 = swBase, w1 = swBase + CHUNK_FLOATS * 4, w2 = swBase + 2 * CHUNK_FLOATS * 4;
    float *p0 = sW, *p1 = sW + CHUNK_FLOATS, *p2 = sW + 2 * CHUNK_FLOATS;

    // ---- L0: chunks 0..5 read sX ----
#pragma unroll
    for (int c = 0; c < 6; ++c) {
        asm volatile("cp.async.wait_group 1;");
        __syncthreads();   // chunk c ready; all threads done with gemm(c-1)
        prefW(c + 2, p2);  // p2 was last read at gemm(c-1): safe after the sync
        cpcommit();
        gemmChunk(aX0 + (c & 1) * 128, aX1 + (c & 1) * 128, w0);
        if (c == 1) epiSig(0);
        else if (c == 3) epiG(1);
        {
            unsigned t = w0; w0 = w1; w1 = w2; w2 = t;
            float* q = p0; p0 = p1; p1 = p2; p2 = q;
        }
    }

    // ---- chunk 6: h0 overwrites the aliased sX region -> extra barrier ----
    asm volatile("cp.async.wait_group 1;");
    __syncthreads();  // all done reading sX (gemm 5)
    epiH(2);          // h0 -> sH (clobbers sX region)
    __syncthreads();  // h0 visible to all warps
    prefW(8, p2);
    cpcommit();
    gemmChunk(aH0, aH1, w0);
    {
        unsigned t = w0; w0 = w1; w1 = w2; w2 = t;
        float* q = p0; p0 = p1; p1 = p2; p2 = q;
    }

    // ---- L1: chunks 7..17 read sH ----
#pragma unroll 1
    for (int c = 7; c < 18; ++c) {
        asm volatile("cp.async.wait_group 1;");
        __syncthreads();
        if (c < 16) prefW(c + 2, p2);
        cpcommit();
        gemmChunk(aH0 + ((c - 6) & 3) * 128, aH1 + ((c - 6) & 3) * 128, w0);
        if (c == 9) epiSig(3);
        else if (c == 13) epiG(4);
        {
            unsigned t = w0; w0 = w1; w1 = w2; w2 = t;
            float* q = p0; p0 = p1; p1 = p2; p2 = q;
        }
    }

    __syncthreads();  // all warps done reading h0 (gemm 17)
    epiH(5);          // h1 -> sH
    __syncthreads();

    // ---- heads on tensor cores (warps 0..3) ----
    float* pol = out;
    float* val = out + (size_t)BATCH * NACT;
    if (wid < 4) {
        float ha[3][4];
#pragma unroll
        for (int nt = 0; nt < 3; nt++)
#pragma unroll
            for (int ci = 0; ci < 4; ci++) ha[nt][ci] = 0.f;
        const unsigned* uA = (const unsigned*)sH;
        const unsigned* uW = (const unsigned*)sWH;
        const int mrowH = wid * 16;
#pragma unroll
        for (int ks = 0; ks < 16; ks++) {
            const unsigned* base = uA + (mrowH + g) * HS + ks * 8 + tg;
            unsigned a0 = base[0], a1 = base[8 * HS], a2 = base[4], a3 = base[8 * HS + 4];
#pragma unroll
            for (int nt = 0; nt < 3; nt++) {
                const unsigned* wb = uW + (nt * 8 + g) * WHS + ks * 8 + tg;
                MMA_TF32(ha[nt], a0, a1, a2, a3, wb[0], wb[4]);
            }
        }
#pragma unroll
        for (int nt = 0; nt < 3; nt++)
#pragma unroll
            for (int ci = 0; ci < 4; ci++) {
                int col = nt * 8 + (tg << 1) + (ci & 1);
                int r = mrowH + g + ((ci >> 1) << 3);
                int gr = rowbase + r;
                if (col < NACT)
                    pol[(size_t)gr * NACT + col] = ha[nt][ci] + bp[col];
                else if (col == NACT)
                    val[gr] = ha[nt][ci] + bv[0];
            }
    }
}

extern "C" void kernel_launch(void* const* d_in, const int* in_sizes, int n_in,
                              void* d_out, int out_size) {
    const float* x    = (const float*)d_in[0];
    const float* Wih0 = (const float*)d_in[1];
    // d_in[2] = Whh0: unused (h=0)
    const float* bih0 = (const float*)d_in[3];
    const float* bhh0 = (const float*)d_in[4];
    const float* Wih1 = (const float*)d_in[5];
    // d_in[6] = Whh1: unused (h=0)
    const float* bih1 = (const float*)d_in[7];
    const float* bhh1 = (const float*)d_in[8];
    const float* Wp   = (const float*)d_in[9];
    const float* bp   = (const float*)d_in[10];
    const float* Wv   = (const float*)d_in[11];
    const float* bv   = (const float*)d_in[12];
    float* out = (float*)d_out;

    cudaFuncSetAttribute(lstm_policy_kernel,
                         cudaFuncAttributeMaxDynamicSharedMemorySize, SMEM_BYTES);

    dim3 grid(BATCH / BM);
    dim3 block(NTHR);
    lstm_policy_kernel<<<grid, block, SMEM_BYTES>>>(
        x, Wih0, bih0, bhh0, Wih1, bih1, bhh1, Wp, bp, Wv, bv, out);
}

// round 9
// speedup vs baseline: 4.4110x; 1.0872x over previous
#include <cuda_runtime.h>
#include <cstdint>

#define BATCH 65536
#define INP 64
#define HID 128
#define NACT 16
#define BM 64
#define NTHR 256

// smem strides (floats); all ≡ 4 (mod 32) -> conflict-free LDSM row addressing
#define XS 68
#define HS 132
#define WS 36
#define WHS 132

// Layout (floats): sH [64x132] at 0 (sX [64x68] ALIASED under it; x dead after chunk 5),
// 3-buffer weight ring, head weights, biases.
#define SW_OFF 8448
#define CHUNK_FLOATS (128 * WS)                  // 4608
#define SWH_OFF (SW_OFF + 3 * CHUNK_FLOATS)      // 22272
#define SB_OFF (SWH_OFF + 24 * WHS)              // 25440
#define SMEM_FLOATS (SB_OFF + 6 * 128)           // 26208
#define SMEM_BYTES (SMEM_FLOATS * 4)             // 104832 B -> 2 CTAs/SM

__device__ __forceinline__ void cpa16(float* dst, const float* src) {
    unsigned u = (unsigned)__cvta_generic_to_shared(dst);
    asm volatile("cp.async.cg.shared.global [%0], [%1], 16;" ::"r"(u), "l"(src));
}
__device__ __forceinline__ void cpcommit() { asm volatile("cp.async.commit_group;"); }

__device__ __forceinline__ float htanh(float v) {
    float r;
    asm("tanh.approx.f32 %0, %1;" : "=f"(r) : "f"(v));
    return r;
}
__device__ __forceinline__ float fsig(float v) {
    return fmaf(htanh(0.5f * v), 0.5f, 0.5f);
}
__device__ __forceinline__ float ftanh(float v) { return htanh(v); }

#define MMA_TF32(d, a0, a1, a2, a3, b0, b1)                                     \
    asm volatile(                                                               \
        "mma.sync.aligned.m16n8k8.row.col.f32.tf32.tf32.f32 "                   \
        "{%0,%1,%2,%3},{%4,%5,%6,%7},{%8,%9},{%0,%1,%2,%3};"                    \
        : "+f"(d[0]), "+f"(d[1]), "+f"(d[2]), "+f"(d[3])                        \
        : "r"(a0), "r"(a1), "r"(a2), "r"(a3), "r"(b0), "r"(b1))

__device__ __forceinline__ void ldsm4(unsigned r[4], unsigned addr) {
    asm volatile("ldmatrix.sync.aligned.m8n8.x4.shared.b16 {%0,%1,%2,%3}, [%4];"
                 : "=r"(r[0]), "=r"(r[1]), "=r"(r[2]), "=r"(r[3])
                 : "r"(addr));
}

__global__ void __launch_bounds__(NTHR, 2)
lstm_policy_kernel(const float* __restrict__ x,
                   const float* __restrict__ Wih0,
                   const float* __restrict__ bih0,
                   const float* __restrict__ bhh0,
                   const float* __restrict__ Wih1,
                   const float* __restrict__ bih1,
                   const float* __restrict__ bhh1,
                   const float* __restrict__ Wp,
                   const float* __restrict__ bp,
                   const float* __restrict__ Wv,
                   const float* __restrict__ bv,
                   float* __restrict__ out) {
    extern __shared__ float sm[];
    float* sH = sm;          // [64][132] h0 then h1
    float* sX = sm;          // [64][68]  x tile, ALIASED (dead after chunk 5)
    float* sW = sm + SW_OFF; // 3 x [128][36] weight ring
    float* sWH = sm + SWH_OFF;
    float* sB = sm + SB_OFF;

    const int tid = threadIdx.x;
    const int wid = tid >> 5, lane = tid & 31;
    const int g = lane >> 2, tg = lane & 3;
    // NEW tiling: each warp owns a UNIQUE B slab of 16 out-cols; full 64 batch rows.
    const int ncolW = wid * 16;  // 8 warps x 16 = 128 out cols
    const int rowbase = blockIdx.x * BM;

    // per-warp slab prefetch: 16 rows x 32 K of chunk c -> ring buffer (c%3).
    // Only THIS warp reads these rows via LDSM -> per-warp wait_group is sufficient;
    // no block barrier needed for the weight pipeline.
    auto prefSlab = [&](int c) {
        const float* src;
        int ld;
        if (c < 6) {
            int gate = c >> 1;
            int gbase = (gate == 0) ? 0 : (gate == 1 ? 256 : 384);
            src = Wih0 + (size_t)gbase * INP + ((c & 1) << 5);
            ld = INP;
        } else {
            int cc = c - 6;
            int gate = cc >> 2;
            int gbase = (gate == 0) ? 0 : (gate == 1 ? 256 : 384);
            src = Wih1 + (size_t)gbase * HID + ((cc & 3) << 5);
            ld = HID;
        }
        float* dst = sW + (c % 3) * CHUNK_FLOATS;
#pragma unroll
        for (int i = 0; i < 4; i++) {
            int idx = lane + i * 32;  // 128 float4 = warp's 16-row slab
            int r = ncolW + (idx >> 3);
            int c4 = idx & 7;
            cpa16(dst + r * WS + c4 * 4, src + (size_t)r * ld + c4 * 4);
        }
    };

    // ---- prologue: G0 = {x, head weights}; G1 = {slab0}; G2 = {slab1} ----
    {
        const float* xs = x + (size_t)rowbase * INP;
#pragma unroll
        for (int i = 0; i < 4; i++) {
            int idx = tid + i * NTHR;  // 1024 float4 (64 rows x 16)
            int r = idx >> 4;
            int c4 = idx & 15;
            cpa16(sX + r * XS + c4 * 4, xs + r * INP + c4 * 4);
        }
#pragma unroll
        for (int idx = tid; idx < 544; idx += NTHR) {  // strided: 544 > NTHR
            int r = idx >> 5, c4 = idx & 31;
            const float* srcp = (r < 16) ? (Wp + r * HID + c4 * 4) : (Wv + c4 * 4);
            cpa16(sWH + r * WHS + c4 * 4, srcp);
        }
        cpcommit();      // G0
        prefSlab(0);
        cpcommit();      // G1
        prefSlab(1);
        cpcommit();      // G2
    }

    // combined biases + zero-pad head rows 17..23 (plain stores; initial barrier covers)
    if (tid < 128) {
        sB[tid] = bih0[tid] + bhh0[tid];
        sB[128 + tid] = bih0[256 + tid] + bhh0[256 + tid];
        sB[256 + tid] = bih0[384 + tid] + bhh0[384 + tid];
        sB[384 + tid] = bih1[tid] + bhh1[tid];
        sB[512 + tid] = bih1[256 + tid] + bhh1[256 + tid];
        sB[640 + tid] = bih1[384 + tid] + bhh1[384 + tid];
    }
#pragma unroll
    for (int idx = tid; idx < 7 * HID; idx += NTHR) {
        int r = 17 + idx / HID, c = idx % HID;
        sWH[r * WHS + c] = 0.f;
    }

    // wait for G0 (x + headW) per-thread, then block barrier -> x/sB/sWH visible to all
    asm volatile("cp.async.wait_group 2;");
    __syncthreads();  // BARRIER 1 of 5

    // ---- LDSM address precompute (same fragment mapping as passing R7/R8) ----
    const int j8 = lane & 7, sel = lane >> 3;
    const int arow = ((sel & 1) << 3) + j8;
    const int acol = (sel >> 1) << 2;
    const unsigned shBase = (unsigned)__cvta_generic_to_shared(sm);
    const unsigned swBase = shBase + SW_OFF * 4;
    const unsigned aX = shBase + (arow * XS + acol) * 4;  // mt offset added below
    const unsigned aH = shBase + (arow * HS + acol) * 4;
    // B slab: one ldsm4 covers rows [ncolW, ncolW+16) x 8 K = nt0/nt1, b0/b1
    const unsigned bO = ((ncolW + ((sel >> 1) << 3) + j8) * WS + ((sel & 1) << 2)) * 4;

    float acc[4][2][4], sc[4][2][4];
#pragma unroll
    for (int mt = 0; mt < 4; mt++)
#pragma unroll
        for (int nt = 0; nt < 2; nt++)
#pragma unroll
            for (int ci = 0; ci < 4; ci++) acc[mt][nt][ci] = 0.f;

    // one K=32 gemm chunk: warp tile 64 rows x 16 cols = 20 LDSM.x4 + 32 MMA
    auto gemmChunk = [&](unsigned aBase, unsigned mtPitch, unsigned wbase) {
#pragma unroll
        for (int ks = 0; ks < 4; ks++) {
            unsigned bf[4];
            ldsm4(bf, wbase + bO + ks * 32);
#pragma unroll
            for (int mt = 0; mt < 4; mt++) {
                unsigned af[4];
                ldsm4(af, aBase + mt * mtPitch + ks * 32);
                MMA_TF32(acc[mt][0], af[0], af[1], af[2], af[3], bf[0], bf[1]);
                MMA_TF32(acc[mt][1], af[0], af[1], af[2], af[3], bf[2], bf[3]);
            }
        }
    };

    auto epiSig = [&](int panel) {
#pragma unroll
        for (int mt = 0; mt < 4; mt++)
#pragma unroll
            for (int nt = 0; nt < 2; nt++)
#pragma unroll
                for (int ci = 0; ci < 4; ci++) {
                    int cc = ncolW + nt * 8 + (tg << 1) + (ci & 1);
                    sc[mt][nt][ci] = fsig(acc[mt][nt][ci] + sB[panel * 128 + cc]);
                    acc[mt][nt][ci] = 0.f;
                }
    };
    auto epiG = [&](int panel) {
#pragma unroll
        for (int mt = 0; mt < 4; mt++)
#pragma unroll
            for (int nt = 0; nt < 2; nt++)
#pragma unroll
                for (int ci = 0; ci < 4; ci++) {
                    int cc = ncolW + nt * 8 + (tg << 1) + (ci & 1);
                    sc[mt][nt][ci] *= ftanh(acc[mt][nt][ci] + sB[panel * 128 + cc]);
                    acc[mt][nt][ci] = 0.f;
                }
    };
    auto epiH = [&](int panel) {
#pragma unroll
        for (int mt = 0; mt < 4; mt++)
#pragma unroll
            for (int nt = 0; nt < 2; nt++)
#pragma unroll
                for (int ci = 0; ci < 4; ci++) {
                    int r = mt * 16 + g + ((ci >> 1) << 3);
                    int cc = ncolW + nt * 8 + (tg << 1) + (ci & 1);
                    float h = fsig(acc[mt][nt][ci] + sB[panel * 128 + cc]) * ftanh(sc[mt][nt][ci]);
                    sH[r * HS + cc] = h;
                    acc[mt][nt][ci] = 0.f;
                }
    };

    // ---- L0: chunks 0..5 read sX; NO block barriers (per-warp slab pipeline) ----
#pragma unroll
    for (int c = 0; c < 6; ++c) {
        asm volatile("cp.async.wait_group 1;");  // per-warp: slab c landed
        if (c + 2 < 18) prefSlab(c + 2);
        cpcommit();
        gemmChunk(aX + (c & 1) * 128, 16 * XS * 4, swBase + (c % 3) * CHUNK_FLOATS * 4);
        if (c == 1) epiSig(0);
        else if (c == 3) epiG(1);
    }

    // ---- layer boundary: h0 overwrites aliased sX region ----
    __syncthreads();  // BARRIER 2: all warps done reading x (gemm 5)
    epiH(2);          // h0 -> sH
    __syncthreads();  // BARRIER 3: h0 visible to all warps

    // ---- L1: chunks 6..17 read sH; NO block barriers ----
#pragma unroll
    for (int c = 6; c < 18; ++c) {
        asm volatile("cp.async.wait_group 1;");
        if (c + 2 < 18) prefSlab(c + 2);
        cpcommit();
        gemmChunk(aH + ((c - 6) & 3) * 128, 16 * HS * 4, swBase + (c % 3) * CHUNK_FLOATS * 4);
        if (c == 9) epiSig(3);
        else if (c == 13) epiG(4);
    }

    __syncthreads();  // BARRIER 4: all warps done reading h0 (gemm 17)
    epiH(5);          // h1 -> sH
    __syncthreads();  // BARRIER 5: h1 visible

    // ---- heads on tensor cores (warps 0..3) ----
    float* pol = out;
    float* val = out + (size_t)BATCH * NACT;
    if (wid < 4) {
        float ha[3][4];
#pragma unroll
        for (int nt = 0; nt < 3; nt++)
#pragma unroll
            for (int ci = 0; ci < 4; ci++) ha[nt][ci] = 0.f;
        const unsigned* uA = (const unsigned*)sH;
        const unsigned* uW = (const unsigned*)sWH;
        const int mrowH = wid * 16;
#pragma unroll
        for (int ks = 0; ks < 16; ks++) {
            const unsigned* base = uA + (mrowH + g) * HS + ks * 8 + tg;
            unsigned a0 = base[0], a1 = base[8 * HS], a2 = base[4], a3 = base[8 * HS + 4];
#pragma unroll
            for (int nt = 0; nt < 3; nt++) {
                const unsigned* wb = uW + (nt * 8 + g) * WHS + ks * 8 + tg;
                MMA_TF32(ha[nt], a0, a1, a2, a3, wb[0], wb[4]);
            }
        }
#pragma unroll
        for (int nt = 0; nt < 3; nt++)
#pragma unroll
            for (int ci = 0; ci < 4; ci++) {
                int col = nt * 8 + (tg << 1) + (ci & 1);
                int r = mrowH + g + ((ci >> 1) << 3);
                int gr = rowbase + r;
                if (col < NACT)
                    pol[(size_t)gr * NACT + col] = ha[nt][ci] + bp[col];
                else if (col == NACT)
                    val[gr] = ha[nt][ci] + bv[0];
            }
    }
}

extern "C" void kernel_launch(void* const* d_in, const int* in_sizes, int n_in,
                              void* d_out, int out_size) {
    const float* x    = (const float*)d_in[0];
    const float* Wih0 = (const float*)d_in[1];
    // d_in[2] = Whh0: unused (h=0)
    const float* bih0 = (const float*)d_in[3];
    const float* bhh0 = (const float*)d_in[4];
    const float* Wih1 = (const float*)d_in[5];
    // d_in[6] = Whh1: unused (h=0)
    const float* bih1 = (const float*)d_in[7];
    const float* bhh1 = (const float*)d_in[8];
    const float* Wp   = (const float*)d_in[9];
    const float* bp   = (const float*)d_in[10];
    const float* Wv   = (const float*)d_in[11];
    const float* bv   = (const float*)d_in[12];
    float* out = (float*)d_out;

    cudaFuncSetAttribute(lstm_policy_kernel,
                         cudaFuncAttributeMaxDynamicSharedMemorySize, SMEM_BYTES);

    dim3 grid(BATCH / BM);
    dim3 block(NTHR);
    lstm_policy_kernel<<<grid, block, SMEM_BYTES>>>(
        x, Wih0, bih0, bhh0, Wih1, bih1, bhh1, Wp, bp, Wv, bv, out);
}